// round 17
// baseline (speedup 1.0000x reference)
#include <cuda_runtime.h>
#include <cuda_bf16.h>
#include <cstdint>

// ---------------------------------------------------------------------------
// StableSpikingCoreFlow, round 17 = round 16 (108.6us, rel_err 0.0) with the
// GEMM inner loops restructured to cut smem-crossbar bytes: B fragments are
// loaded ONCE per kk (hoisted out of the mt loop) and A fragments once per
// kk. Per-accumulator MMA order is unchanged (bit-identical numerics).
// ---------------------------------------------------------------------------

#define Bc 128
#define Dc 2048
#define Nc 2048
#define Tc 64
#define OUTc 1024
#define SPLITK 4
#define GT  512

#define ROWB 144             // 64 bf16 (128B) + 16B pad
#define ATILE (128 * ROWB)   // 18432 B
#define BT64  (64 * ROWB)    //  9216 B
#define BUF1  (ATILE + 3 * BT64)
#define SMEM1 (2 * BUF1)     // 92160 B
#define BUFG  (3 * ATILE + 3 * BT64)   // 82944 B
#define SMEMG (2 * BUFG)               // 165888 B

#define APIECE (Bc * Dc)
#define PL (Bc * Nc)

__device__ __nv_bfloat16 g_A[3 * APIECE];
__device__ float g_P[SPLITK * PL];

// ---------------------------------------------------------------------------
__device__ __forceinline__ void cp16(uint32_t dst, const void* src) {
    asm volatile("cp.async.cg.shared.global [%0], [%1], 16;\n" :: "r"(dst), "l"(src));
}
#define CP_COMMIT() asm volatile("cp.async.commit_group;\n" ::: "memory")
#define CP_WAIT(n)  asm volatile("cp.async.wait_group %0;\n" :: "n"(n) : "memory")

__device__ __forceinline__ void mma16816(float* c, const uint32_t* a,
                                         uint32_t b0, uint32_t b1) {
    asm volatile(
        "mma.sync.aligned.m16n8k16.row.col.f32.bf16.bf16.f32 "
        "{%0,%1,%2,%3},{%4,%5,%6,%7},{%8,%9},{%0,%1,%2,%3};\n"
        : "+f"(c[0]), "+f"(c[1]), "+f"(c[2]), "+f"(c[3])
        : "r"(a[0]), "r"(a[1]), "r"(a[2]), "r"(a[3]), "r"(b0), "r"(b1));
}

__device__ __forceinline__ uint32_t lds32c(const char* p) {
    return *(const uint32_t*)p;
}

__device__ __forceinline__ float bfround(float v) {
    return __bfloat162float(__float2bfloat16_rn(v));
}
__device__ __forceinline__ unsigned bfu(float v) {
    return (unsigned)__bfloat16_as_ushort(__float2bfloat16_rn(v));
}
__device__ __forceinline__ uint32_t pk(unsigned lo, unsigned hi) {
    return lo | (hi << 16);
}
// v = p0+p1+p2 + O(2^-25 v); residual subtractions exact
__device__ __forceinline__ void split3(float v, unsigned& u0, unsigned& u1,
                                       unsigned& u2) {
    float r1 = v - bfround(v);
    float r2 = r1 - bfround(r1);
    u0 = bfu(v); u1 = bfu(r1); u2 = bfu(r2);
}

// exact fp32 semantics of the reference spike scan; returns COUNT (0..64)
__device__ __forceinline__ float spike_count(float a, float thr) {
    int c;
    if (a <= 0.f) c = 0;
    else if (a > thr) c = Tc;
    else {
        float m = 0.f; c = 0;
        for (int t = 0; t < Tc; t++) { m += a; if (m > thr) { m -= thr; c++; } }
    }
    return (float)c;
}

// fixed-order tree-4 merge of splitK planes at column idx, then exact /64
__device__ __forceinline__ float plane_avg(int idx) {
    float e0 = g_P[idx];
    float e1 = g_P[PL + idx];
    float e2 = g_P[2 * PL + idx];
    float e3 = g_P[3 * PL + idx];
    return __fadd_rn(__fadd_rn(e0, e1), __fadd_rn(e2, e3)) * 0.015625f;
}

#define KFOLD(acc, ks, kc) do {                                      \
        float y = __fsub_rn((acc), (kc));                            \
        float t = __fadd_rn((ks), y);                                \
        (kc) = __fsub_rn(__fsub_rn(t, (ks)), y);                     \
        (ks) = t;                                                    \
        (acc) = 0.f;                                                 \
    } while (0)

// W split of 8 floats -> 3 pieces, one st.v4.b32 per piece
#define WSPLIT8_STS(base, e8) do {                                   \
        unsigned q0[8], q1[8], q2[8];                                \
        _Pragma("unroll")                                            \
        for (int i = 0; i < 8; i++) split3((e8)[i], q0[i], q1[i], q2[i]); \
        asm volatile("st.shared.v4.b32 [%0], {%1,%2,%3,%4};\n"       \
            :: "r"(base), "r"(pk(q0[0], q0[1])), "r"(pk(q0[2], q0[3])), \
               "r"(pk(q0[4], q0[5])), "r"(pk(q0[6], q0[7])));        \
        asm volatile("st.shared.v4.b32 [%0], {%1,%2,%3,%4};\n"       \
            :: "r"((base) + BT64), "r"(pk(q1[0], q1[1])), "r"(pk(q1[2], q1[3])), \
               "r"(pk(q1[4], q1[5])), "r"(pk(q1[6], q1[7])));        \
        asm volatile("st.shared.v4.b32 [%0], {%1,%2,%3,%4};\n"       \
            :: "r"((base) + 2 * BT64), "r"(pk(q2[0], q2[1])), "r"(pk(q2[2], q2[3])), \
               "r"(pk(q2[4], q2[5])), "r"(pk(q2[6], q2[7])));        \
    } while (0)

// ---------------------------------------------------------------------------
// layer-0 prep: gather + split 64*x into 3 bf16 piece matrices
__global__ void prep0a_kernel(const float* __restrict__ x,
                              const int* __restrict__ axon) {
    int idx = blockIdx.x * blockDim.x + threadIdx.x;
    if (idx >= Bc * Dc / 2) return;
    int b = idx >> 10, a = (idx & 1023) * 2;
    unsigned p0, p1, p2, q0, q1, q2;
    split3(64.0f * x[(b << 11) + axon[a]],     p0, p1, p2);
    split3(64.0f * x[(b << 11) + axon[a + 1]], q0, q1, q2);
    size_t off = (size_t)b * Dc + a;
    *(uint32_t*)(g_A + off)              = pk(p0, q0);
    *(uint32_t*)(g_A + APIECE + off)     = pk(p1, q1);
    *(uint32_t*)(g_A + 2 * APIECE + off) = pk(p2, q2);
}

// layers>=1 prep: spike counts computed at the gather site from the planes
__global__ void prepA_kernel(const int* __restrict__ axon,
                             const float* __restrict__ thr, int lprev) {
    int idx = blockIdx.x * blockDim.x + threadIdx.x;
    if (idx >= Bc * Dc / 2) return;
    int b = idx >> 10, a = (idx & 1023) * 2;
    int i0 = axon[a], i1 = axon[a + 1];
    const float th = thr[lprev];
    float c0 = spike_count(plane_avg((b << 11) + i0), th);
    float c1 = spike_count(plane_avg((b << 11) + i1), th);
    *(uint32_t*)(g_A + (size_t)b * Dc + a) = pk(bfu(c0), bfu(c1));
}

// final output: spike counts at out_idx columns from the planes
__global__ void outF_kernel(const int* __restrict__ out_idx,
                            const float* __restrict__ thr,
                            float* __restrict__ out) {
    int idx = blockIdx.x * blockDim.x + threadIdx.x;
    if (idx >= Bc * OUTc) return;
    int b = idx >> 10, o = idx & 1023;
    int n = out_idx[o];
    out[idx] = spike_count(plane_avg((b << 11) + n), thr[3]);
}

// ---------------------------------------------------------------------------
// layer-0 GEMM: 512 threads, 16 warps (4m x 4n), warp tile 32m x 16n.
// Fragments loaded once per kk; per-acc MMA order unchanged (6-pair seq).
__global__ __launch_bounds__(GT, 1)
void gemm0s_kernel(const float* __restrict__ W) {
    extern __shared__ char smch[];
    const int tid = threadIdx.x;
    const int w = tid >> 5, lane = tid & 31;
    const int wm = w & 3, wn = w >> 2;
    const int g = lane >> 2, tig = lane & 3;
    const int bn = blockIdx.x * 64;
    const size_t k0 = (size_t)blockIdx.y * (Dc / SPLITK);
    const uint32_t smb = (uint32_t)__cvta_generic_to_shared(smch);
    const int nPh = (Dc / SPLITK) / 64;   // 8

    const int ch = tid & 7;
    const int arow0 = tid >> 3;
    const int vrow = tid >> 3;
    const int vq   = tid & 7;
    const float* wp = W + (size_t)(bn + vrow) * Dc + k0 + vq * 8;
    const uint32_t bsts = smb + 3 * ATILE + vrow * ROWB + vq * 16;

#define FA0(p, buf) do {                                                     \
        uint32_t bo = (uint32_t)(buf) * BUFG;                                \
        _Pragma("unroll")                                                    \
        for (int pc = 0; pc < 3; pc++)                                       \
            _Pragma("unroll")                                                \
            for (int r = 0; r < 2; r++)                                      \
                cp16(smb + bo + pc * ATILE + (arow0 + r * 64) * ROWB + ch * 16, \
                     g_A + pc * APIECE + (size_t)(arow0 + r * 64) * Dc + k0  \
                         + ch * 8 + (size_t)(p) * 64);                       \
        CP_COMMIT();                                                         \
    } while (0)

#define WLOAD(wr, p) do {                                                    \
        wr[0] = *(const float4*)(wp + (size_t)(p) * 64);                     \
        wr[1] = *(const float4*)(wp + (size_t)(p) * 64 + 4);                 \
    } while (0)

#define FB0(buf, wr) do {                                                    \
        float e8[8] = {wr[0].x, wr[0].y, wr[0].z, wr[0].w,                   \
                       wr[1].x, wr[1].y, wr[1].z, wr[1].w};                  \
        WSPLIT8_STS(bsts + (uint32_t)(buf) * BUFG, e8);                      \
    } while (0)

    float acc[2][2][4], ks[2][2][4], kc[2][2][4];
#pragma unroll
    for (int mt = 0; mt < 2; mt++)
#pragma unroll
        for (int j = 0; j < 2; j++)
#pragma unroll
            for (int q = 0; q < 4; q++) {
                acc[mt][j][q] = 0.f; ks[mt][j][q] = 0.f; kc[mt][j][q] = 0.f;
            }

    float4 wr[2];
    WLOAD(wr, 0); FB0(0, wr); FA0(0, 0);
    WLOAD(wr, 1); FB0(1, wr); FA0(1, 1);
    WLOAD(wr, 2);

    for (int p = 0; p < nPh; p++) {
        if (p + 1 < nPh) { CP_WAIT(1); } else { CP_WAIT(0); }
        __syncthreads();
        const char* Ab = smch + (p & 1) * BUFG;
        const char* Bb = Ab + 3 * ATILE;
#pragma unroll
        for (int kk = 0; kk < 4; kk++) {
            // load ALL fragments for this kk once
            uint32_t a[3][2][4];
#pragma unroll
            for (int pc = 0; pc < 3; pc++)
#pragma unroll
                for (int mt = 0; mt < 2; mt++) {
                    const char* ap = Ab + pc * ATILE
                                   + (wm * 32 + mt * 16 + g) * ROWB
                                   + kk * 32 + tig * 4;
                    a[pc][mt][0] = lds32c(ap);
                    a[pc][mt][1] = lds32c(ap + 8 * ROWB);
                    a[pc][mt][2] = lds32c(ap + 16);
                    a[pc][mt][3] = lds32c(ap + 8 * ROWB + 16);
                }
            uint32_t b[3][2][2];
#pragma unroll
            for (int j = 0; j < 2; j++) {
                const char* brow = Bb + (wn * 16 + j * 8 + g) * ROWB
                                 + kk * 32 + tig * 4;
#pragma unroll
                for (int pc = 0; pc < 3; pc++) {
                    b[pc][j][0] = lds32c(brow + pc * BT64);
                    b[pc][j][1] = lds32c(brow + pc * BT64 + 16);
                }
            }
            // MMA: per-acc order = a0w0,a0w1,a0w2,a1w0,a1w1,a2w0 (unchanged)
#pragma unroll
            for (int mt = 0; mt < 2; mt++)
#pragma unroll
                for (int j = 0; j < 2; j++) {
                    mma16816(acc[mt][j], a[0][mt], b[0][j][0], b[0][j][1]);
                    mma16816(acc[mt][j], a[0][mt], b[1][j][0], b[1][j][1]);
                    mma16816(acc[mt][j], a[0][mt], b[2][j][0], b[2][j][1]);
                    mma16816(acc[mt][j], a[1][mt], b[0][j][0], b[0][j][1]);
                    mma16816(acc[mt][j], a[1][mt], b[1][j][0], b[1][j][1]);
                    mma16816(acc[mt][j], a[2][mt], b[0][j][0], b[0][j][1]);
                }
            // Kahan fold every kk (round-14 cadence, measured 0.0)
#pragma unroll
            for (int mt = 0; mt < 2; mt++)
#pragma unroll
                for (int j = 0; j < 2; j++)
#pragma unroll
                    for (int q = 0; q < 4; q++)
                        KFOLD(acc[mt][j][q], ks[mt][j][q], kc[mt][j][q]);
        }
        __syncthreads();
        if (p + 2 < nPh) {
            FB0(p & 1, wr);
            FA0(p + 2, p & 1);
            if (p + 3 < nPh) WLOAD(wr, p + 3);
        }
    }
#undef FA0
#undef FB0
#undef WLOAD

    float* plane = g_P + (size_t)blockIdx.y * PL;
#pragma unroll
    for (int mt = 0; mt < 2; mt++)
#pragma unroll
        for (int j = 0; j < 2; j++) {
            int m = wm * 32 + mt * 16 + g;
            int n = bn + wn * 16 + j * 8 + 2 * tig;
            float r0 = __fsub_rn(ks[mt][j][0], kc[mt][j][0]);
            float r1 = __fsub_rn(ks[mt][j][1], kc[mt][j][1]);
            float r2 = __fsub_rn(ks[mt][j][2], kc[mt][j][2]);
            float r3 = __fsub_rn(ks[mt][j][3], kc[mt][j][3]);
            *(float2*)&plane[(size_t)m * Nc + n]       = make_float2(r0, r1);
            *(float2*)&plane[(size_t)(m + 8) * Nc + n] = make_float2(r2, r3);
        }
}

// ---------------------------------------------------------------------------
// layers>=1 GEMM: 512 threads, 16 warps, warp tile 32m x 16n; fragments
// loaded once per kk (B hoisted across mt); per-acc MMA order unchanged.
__global__ __launch_bounds__(GT, 1)
void gemm1s_kernel(const float* __restrict__ W) {
    extern __shared__ char smch[];
    const int tid = threadIdx.x;
    const int w = tid >> 5, lane = tid & 31;
    const int wm = w & 3, wn = w >> 2;
    const int g = lane >> 2, tig = lane & 3;
    const int bn = blockIdx.x * 64;
    const size_t k0 = (size_t)blockIdx.y * (Dc / SPLITK);
    const uint32_t smb = (uint32_t)__cvta_generic_to_shared(smch);
    const int nPh = (Dc / SPLITK) / 64;   // 8

    const int ch = tid & 7;
    const int arow0 = tid >> 3;
    const int vrow = tid >> 3;
    const int vq   = tid & 7;
    const float* wp = W + (size_t)(bn + vrow) * Dc + k0 + vq * 8;
    const uint32_t bsts = smb + ATILE + vrow * ROWB + vq * 16;

#define FA(p, buf) do {                                                      \
        uint32_t bo = (uint32_t)(buf) * BUF1;                                \
        _Pragma("unroll")                                                    \
        for (int r = 0; r < 2; r++)                                          \
            cp16(smb + bo + (arow0 + r * 64) * ROWB + ch * 16,               \
                 g_A + (size_t)(arow0 + r * 64) * Dc + k0 + ch * 8           \
                     + (size_t)(p) * 64);                                    \
        CP_COMMIT();                                                         \
    } while (0)

#define WLOAD(wr, p) do {                                                    \
        wr[0] = *(const float4*)(wp + (size_t)(p) * 64);                     \
        wr[1] = *(const float4*)(wp + (size_t)(p) * 64 + 4);                 \
    } while (0)

#define FB(buf, wr) do {                                                     \
        float e8[8] = {wr[0].x, wr[0].y, wr[0].z, wr[0].w,                   \
                       wr[1].x, wr[1].y, wr[1].z, wr[1].w};                  \
        WSPLIT8_STS(bsts + (uint32_t)(buf) * BUF1, e8);                      \
    } while (0)

    float acc[2][2][4], ks[2][2][4], kc[2][2][4];
#pragma unroll
    for (int mt = 0; mt < 2; mt++)
#pragma unroll
        for (int j = 0; j < 2; j++)
#pragma unroll
            for (int q = 0; q < 4; q++) {
                acc[mt][j][q] = 0.f; ks[mt][j][q] = 0.f; kc[mt][j][q] = 0.f;
            }

    float4 wr[2];
    WLOAD(wr, 0); FB(0, wr); FA(0, 0);
    WLOAD(wr, 1); FB(1, wr); FA(1, 1);
    WLOAD(wr, 2);

    for (int p = 0; p < nPh; p++) {
        if (p + 1 < nPh) { CP_WAIT(1); } else { CP_WAIT(0); }
        __syncthreads();
        const char* Ab = smch + (p & 1) * BUF1;
        const char* Bb = Ab + ATILE;
#pragma unroll
        for (int kk = 0; kk < 4; kk++) {
            uint32_t a[2][4];
#pragma unroll
            for (int mt = 0; mt < 2; mt++) {
                const char* ap = Ab + (wm * 32 + mt * 16 + g) * ROWB
                               + kk * 32 + tig * 4;
                a[mt][0] = lds32c(ap);
                a[mt][1] = lds32c(ap + 8 * ROWB);
                a[mt][2] = lds32c(ap + 16);
                a[mt][3] = lds32c(ap + 8 * ROWB + 16);
            }
            uint32_t b[3][2][2];
#pragma unroll
            for (int j = 0; j < 2; j++) {
                const char* brow = Bb + (wn * 16 + j * 8 + g) * ROWB
                                 + kk * 32 + tig * 4;
#pragma unroll
                for (int pc = 0; pc < 3; pc++) {
                    b[pc][j][0] = lds32c(brow + pc * BT64);
                    b[pc][j][1] = lds32c(brow + pc * BT64 + 16);
                }
            }
            // per-acc order: pc ascending (unchanged from rounds 12-16)
#pragma unroll
            for (int pc = 0; pc < 3; pc++)
#pragma unroll
                for (int j = 0; j < 2; j++)
#pragma unroll
                    for (int mt = 0; mt < 2; mt++)
                        mma16816(acc[mt][j], a[mt], b[pc][j][0], b[pc][j][1]);
        }
        __syncthreads();
        if (p + 2 < nPh) {
            FB(p & 1, wr);
            FA(p + 2, p & 1);
            if (p + 3 < nPh) WLOAD(wr, p + 3);
        }

        // Kahan fold per phase (round-12/14/15/16 cadence, measured 0.0)
#pragma unroll
        for (int mt = 0; mt < 2; mt++)
#pragma unroll
            for (int j = 0; j < 2; j++)
#pragma unroll
                for (int q = 0; q < 4; q++)
                    KFOLD(acc[mt][j][q], ks[mt][j][q], kc[mt][j][q]);
    }
#undef FA
#undef FB
#undef WLOAD

    float* plane = g_P + (size_t)blockIdx.y * PL;
#pragma unroll
    for (int mt = 0; mt < 2; mt++)
#pragma unroll
        for (int j = 0; j < 2; j++) {
            int m = wm * 32 + mt * 16 + g;
            int n = bn + wn * 16 + j * 8 + 2 * tig;
            float r0 = __fsub_rn(ks[mt][j][0], kc[mt][j][0]);
            float r1 = __fsub_rn(ks[mt][j][1], kc[mt][j][1]);
            float r2 = __fsub_rn(ks[mt][j][2], kc[mt][j][2]);
            float r3 = __fsub_rn(ks[mt][j][3], kc[mt][j][3]);
            *(float2*)&plane[(size_t)m * Nc + n]       = make_float2(r0, r1);
            *(float2*)&plane[(size_t)(m + 8) * Nc + n] = make_float2(r2, r3);
        }
}

// ---------------------------------------------------------------------------
extern "C" void kernel_launch(void* const* d_in, const int* in_sizes, int n_in,
                              void* d_out, int out_size)
{
    const float* x       = (const float*)d_in[0];
    const float* W       = (const float*)d_in[1];
    const float* thr     = (const float*)d_in[2];
    const int*   axon    = (const int*)  d_in[3];
    const int*   out_idx = (const int*)  d_in[4];
    (void)in_sizes; (void)n_in; (void)out_size;

    cudaFuncSetAttribute(gemm0s_kernel,
                         cudaFuncAttributeMaxDynamicSharedMemorySize, SMEMG);
    cudaFuncSetAttribute(gemm1s_kernel,
                         cudaFuncAttributeMaxDynamicSharedMemorySize, SMEM1);

    // layer 0
    prep0a_kernel<<<512, 256>>>(x, axon);
    gemm0s_kernel<<<dim3(32, SPLITK), GT, SMEMG>>>(W);

    // layers 1..3: gather+spike-count fused (reads planes), then GEMM
    for (int l = 1; l < 4; l++) {
        prepA_kernel<<<512, 256>>>(axon + l * Dc, thr, l - 1);
        gemm1s_kernel<<<dim3(32, SPLITK), GT, SMEM1>>>(
            W + (size_t)l * Nc * Dc);
    }

    // final output: spike counts at out_idx straight from the planes
    outF_kernel<<<512, 256>>>(out_idx, thr, (float*)d_out);
}